// round 15
// baseline (speedup 1.0000x reference)
#include <cuda_runtime.h>
#include <cstdint>

// ---------------------------------------------------------------- dims
#define T_STEPS 32
#define B_DIM   256
#define F_DIM   2048
#define H_DIM   4096
#define M_DIM   (T_STEPS * B_DIM)   // 8192
#define K_DIM   F_DIM               // 2048
#define N_DIM   H_DIM               // 4096
#define BH      (B_DIM * H_DIM)     // 1048576

// ---------------------------------------------------------------- fused GEMM + LIF
// Split-pipeline edition: each CTA = two INDEPENDENT 128-thread pipelines
// (N-halves). Each half owns a private A copy + B-half in smem (4-buffer
// ring) and syncs with a named bar.sync over 128 threads. Warps w and w+4
// share an SMSP but belong to different pipelines -> stall decorrelation.
// Per-element fp32 op stream identical to round 13 -> bit-exact.
#define BM    128
#define BN    128                    // per CTA; 64 per half
#define BK    16
#define ASTR  132
#define BSTR  68
#define A_F   (BK * ASTR)            // 2112 floats
#define B_F   (BK * BSTR)            // 1088 floats
#define BUF_F (A_F + B_F)            // 3200 floats per buffer
#define HALF_F (4 * BUF_F)           // 12800 floats per half
#define SMEM_DYN (2 * HALF_F * 4)    // 102400 bytes
#define CSTR  132

__global__ __launch_bounds__(256, 2)
void gemm_lif_fused(const float* __restrict__ A,
                    const float* __restrict__ W,
                    const float* __restrict__ bias,
                    float* __restrict__ out)
{
    extern __shared__ __align__(16) float sm[];

    const int tid   = threadIdx.x;
    const int halfN = tid >> 7;           // 0..1 : pipeline id (N-half)
    const int htid  = tid & 127;
    const int lane  = htid & 31;
    const int hwid  = htid >> 5;          // 0..3 warp-in-half
    const int wm    = hwid >> 1;          // 0..1 row half (64 rows)
    const int wn    = hwid & 1;           // 0..1 col quarter (32 cols)
    const int lr    = lane >> 2;          // 0..7
    const int lc    = lane & 3;           // 0..3

    const int aRow = wm * 64 + lr * 8;    // 8 rows in tile
    const int bCol = wn * 32 + lc * 8;    // 8 cols within the half (0..63)

    const int rowBase = blockIdx.y * BM;  // permuted row space
    const int colBase = blockIdx.x * BN;

    float* hb = sm + halfN * HALF_F;      // this half's buffer base

    // ---- loader indices: per half, 128 threads load A(128x16)+B(64x16)
    const int rA0 = htid >> 2;            // 0..31 (rows rA0 + j*32)
    const int kq  = (htid & 3) << 2;      // 0,4,8,12

    // A pointers (4 chunks, rows rA0 + j*32), permuted rows
    const float* Ap[4];
#pragma unroll
    for (int j = 0; j < 4; j++) {
        int rp = rowBase + rA0 + j * 32;
        Ap[j] = A + (size_t)(((rp & 31) << 8) + (rp >> 5)) * K_DIM + kq;
    }
    // B pointers (2 chunks, W rows colBase + halfN*64 + rA0 + j*32)
    const float* Wp[2];
#pragma unroll
    for (int j = 0; j < 2; j++)
        Wp[j] = W + (size_t)(colBase + halfN * 64 + rA0 + j * 32) * K_DIM + kq;

    float acc[8][8];
#pragma unroll
    for (int i = 0; i < 8; i++)
#pragma unroll
        for (int j = 0; j < 8; j++) acc[i][j] = 0.0f;

    float4 av[4], bv[2];

#define HBAR() asm volatile("bar.sync %0, %1;" :: "r"(halfN + 1), "r"(128) : "memory")

#define LDG_CHUNK(c)                                                          \
    do {                                                                      \
        const size_t off_ = (size_t)(c) * BK;                                 \
        av[0] = *(const float4*)(Ap[0] + off_);                               \
        av[1] = *(const float4*)(Ap[1] + off_);                               \
        av[2] = *(const float4*)(Ap[2] + off_);                               \
        av[3] = *(const float4*)(Ap[3] + off_);                               \
        bv[0] = *(const float4*)(Wp[0] + off_);                               \
        bv[1] = *(const float4*)(Wp[1] + off_);                               \
    } while (0)

#define STS_CHUNK(buf)                                                        \
    do {                                                                      \
        float* As_ = hb + (buf) * BUF_F;                                      \
        float* Bs_ = As_ + A_F;                                               \
        _Pragma("unroll")                                                     \
        for (int j = 0; j < 4; j++) {                                         \
            const int r_ = rA0 + j * 32;                                      \
            As_[(kq + 0) * ASTR + r_] = av[j].x;                              \
            As_[(kq + 1) * ASTR + r_] = av[j].y;                              \
            As_[(kq + 2) * ASTR + r_] = av[j].z;                              \
            As_[(kq + 3) * ASTR + r_] = av[j].w;                              \
        }                                                                     \
        _Pragma("unroll")                                                     \
        for (int j = 0; j < 2; j++) {                                         \
            const int r_ = rA0 + j * 32;                                      \
            Bs_[(kq + 0) * BSTR + r_] = bv[j].x;                              \
            Bs_[(kq + 1) * BSTR + r_] = bv[j].y;                              \
            Bs_[(kq + 2) * BSTR + r_] = bv[j].z;                              \
            Bs_[(kq + 3) * BSTR + r_] = bv[j].w;                              \
        }                                                                     \
    } while (0)

#define COMPUTE(buf)                                                          \
    do {                                                                      \
        const float* As_ = hb + (buf) * BUF_F;                                \
        const float* Bs_ = As_ + A_F;                                         \
        _Pragma("unroll")                                                     \
        for (int k = 0; k < BK; k++) {                                        \
            float a[8], b[8];                                                 \
            float4 t0 = *(const float4*)&As_[k * ASTR + aRow];                \
            float4 t1 = *(const float4*)&As_[k * ASTR + aRow + 4];            \
            a[0] = t0.x; a[1] = t0.y; a[2] = t0.z; a[3] = t0.w;               \
            a[4] = t1.x; a[5] = t1.y; a[6] = t1.z; a[7] = t1.w;               \
            float4 u0 = *(const float4*)&Bs_[k * BSTR + bCol];                \
            float4 u1 = *(const float4*)&Bs_[k * BSTR + bCol + 4];            \
            b[0] = u0.x; b[1] = u0.y; b[2] = u0.z; b[3] = u0.w;               \
            b[4] = u1.x; b[5] = u1.y; b[6] = u1.z; b[7] = u1.w;               \
            _Pragma("unroll")                                                 \
            for (int ii = 0; ii < 8; ii++)                                    \
                _Pragma("unroll")                                             \
                for (int jj = 0; jj < 8; jj++)                                \
                    acc[ii][jj] = fmaf(a[ii], b[jj], acc[ii][jj]);            \
        }                                                                     \
    } while (0)

    // prologue: chunks 0,1 -> buffers 0,1 (per half)
    LDG_CHUNK(0);
    STS_CHUNK(0);
    LDG_CHUNK(1);
    STS_CHUNK(1);
    HBAR();

    const int NIT = K_DIM / BK;   // 128 (even)
#pragma unroll 1
    for (int it = 0; it < NIT; it += 2) {
        if (it + 2 < NIT) LDG_CHUNK(it + 2);
        COMPUTE(it & 3);
        if (it + 2 < NIT) STS_CHUNK((it + 2) & 3);

        if (it + 3 < NIT) LDG_CHUNK(it + 3);
        COMPUTE((it + 1) & 3);
        if (it + 3 < NIT) STS_CHUNK((it + 3) & 3);

        HBAR();   // one 128-thread barrier per 2 iterations
    }

    __syncthreads();   // full CTA: both pipelines done before smem reuse

    // ---------------- fused epilogue: bias + LIF scan -----------------------
    float bb[8];
    {
        const float* bp = bias + colBase + halfN * 64 + bCol;
        float4 q0 = *(const float4*)(bp + 0);
        float4 q1 = *(const float4*)(bp + 4);
        bb[0] = q0.x; bb[1] = q0.y; bb[2] = q0.z; bb[3] = q0.w;
        bb[4] = q1.x; bb[5] = q1.y; bb[6] = q1.z; bb[7] = q1.w;
    }

    float* Cs = sm;   // 64 x CSTR floats = 33792 B <= 102400 B

#pragma unroll 1
    for (int rh = 0; rh < 2; rh++) {
        if (wm == rh) {
            const int rloc = lr * 8;
            const int cOff = halfN * 64 + bCol;
#pragma unroll
            for (int i = 0; i < 8; i++) {
                float* cp = Cs + (rloc + i) * CSTR + cOff;
                float4 v0, v1;
                v0.x = acc[i][0] + bb[0];
                v0.y = acc[i][1] + bb[1];
                v0.z = acc[i][2] + bb[2];
                v0.w = acc[i][3] + bb[3];
                v1.x = acc[i][4] + bb[4];
                v1.y = acc[i][5] + bb[5];
                v1.z = acc[i][6] + bb[6];
                v1.w = acc[i][7] + bb[7];
                *(float4*)(cp + 0) = v0;
                *(float4*)(cp + 4) = v1;
            }
        }
        __syncthreads();

        {
            const int blocal = tid >> 7;          // 0..1
            const int col    = tid & 127;         // 0..127
            const int bG     = blockIdx.y * 4 + rh * 2 + blocal;
            float* ob = out + (size_t)bG * H_DIM + colBase + col;
            const float* cs = Cs + (blocal * 32) * CSTR + col;
            float v = 0.0f, cnt = 0.0f;
#pragma unroll
            for (int t = 0; t < T_STEPS; t++) {
                float x = cs[t * CSTR];
                v = __fadd_rn(v, __fmul_rn(__fsub_rn(x, v), 0.5f));
                bool fire = (v >= 1.0f);
                float s = fire ? 1.0f : 0.0f;
                ob[(size_t)t * BH] = s;
                cnt += s;
                v = fire ? 0.0f : v;
            }
            ob[(size_t)T_STEPS * BH] = cnt;       // count block after spk_seq
        }
        __syncthreads();
    }
}

// ---------------------------------------------------------------- launch
extern "C" void kernel_launch(void* const* d_in, const int* in_sizes, int n_in,
                              void* d_out, int out_size)
{
    const float* x_seq = (const float*)d_in[0];  // [T,B,F]
    const float* W     = (const float*)d_in[1];  // [H,F]
    const float* b     = (const float*)d_in[2];  // [H]
    float* out = (float*)d_out;

    cudaFuncSetAttribute(gemm_lif_fused,
                         cudaFuncAttributeMaxDynamicSharedMemorySize, SMEM_DYN);

    dim3 gg(N_DIM / BN, M_DIM / BM);   // (32, 64)
    gemm_lif_fused<<<gg, 256, SMEM_DYN>>>(x_seq, W, b, out);
}

// round 16
// speedup vs baseline: 1.1474x; 1.1474x over previous
#include <cuda_runtime.h>
#include <cstdint>

// ---------------------------------------------------------------- dims
#define T_STEPS 32
#define B_DIM   256
#define F_DIM   2048
#define H_DIM   4096
#define M_DIM   (T_STEPS * B_DIM)   // 8192
#define K_DIM   F_DIM               // 2048
#define N_DIM   H_DIM               // 4096
#define BH      (B_DIM * H_DIM)     // 1048576

// ---------------------------------------------------------------- fused GEMM + LIF
// Round-13 winner with ONE change: 6 smem buffers, one __syncthreads per
// THREE k-iterations (43 barriers vs 64). Loader, lane mapping, and fp32
// op stream identical to round 13 -> bit-exact (rel_err 0.0).
#define BM  128
#define BN  128
#define BK  16
#define PAD 4
#define STR (BM + PAD)                       // 132
#define STAGE_F (BK * STR)                   // 2112 floats per array per stage
#define NBUF 6
#define SMEM_DYN (NBUF * 2 * STAGE_F * 4)    // 101376 bytes
#define CSTR 132

__global__ __launch_bounds__(256, 2)
void gemm_lif_fused(const float* __restrict__ A,
                    const float* __restrict__ W,
                    const float* __restrict__ bias,
                    float* __restrict__ out)
{
    extern __shared__ __align__(16) float sm[];
    // buffer s: As_s = sm + s*2*STAGE_F ; Bs_s = As_s + STAGE_F

    const int tid  = threadIdx.x;
    const int lane = tid & 31;
    const int wid  = tid >> 5;
    const int wm   = wid >> 2;            // 0..1 warp row (64 rows)
    const int wn   = wid & 3;             // 0..3 warp col (32 cols)
    const int lr   = lane >> 2;           // 0..7 lane row
    const int lc   = lane & 3;            // 0..3 lane col

    const int aRow = wm * 64 + lr * 8;
    const int bCol = wn * 32 + lc * 8;

    const int rowBase = blockIdx.y * BM;  // permuted row space
    const int colBase = blockIdx.x * BN;

    // loader indices — round-10/13 (8 lines per warp-LDG)
    const int r0 = tid >> 2;          // 0..63
    const int r1 = r0 + 64;           // 64..127
    const int kq = (tid & 3) << 2;    // 0,4,8,12

    // permuted A rows: local r -> global row ((r'&31)*256 + (r'>>5))
    const int rp0 = rowBase + r0;
    const int rp1 = rowBase + r1;
    const float* ApA = A + (size_t)(((rp0 & 31) << 8) + (rp0 >> 5)) * K_DIM + kq;
    const float* ApB = A + (size_t)(((rp1 & 31) << 8) + (rp1 >> 5)) * K_DIM + kq;
    const float* WpA = W + (size_t)(colBase + r0) * K_DIM + kq;
    const float* WpB = W + (size_t)(colBase + r1) * K_DIM + kq;

    float acc[8][8];
#pragma unroll
    for (int i = 0; i < 8; i++)
#pragma unroll
        for (int j = 0; j < 8; j++) acc[i][j] = 0.0f;

    float4 av0, av1, bv0, bv1;

#define LDG_CHUNK(c)                                                          \
    do {                                                                      \
        const size_t off_ = (size_t)(c) * BK;                                 \
        av0 = *(const float4*)(ApA + off_);                                   \
        av1 = *(const float4*)(ApB + off_);                                   \
        bv0 = *(const float4*)(WpA + off_);                                   \
        bv1 = *(const float4*)(WpB + off_);                                   \
    } while (0)

#define STS_CHUNK(buf)                                                        \
    do {                                                                      \
        float* As_ = sm + (buf) * 2 * STAGE_F;                                \
        float* Bs_ = As_ + STAGE_F;                                           \
        As_[(kq + 0) * STR + r0] = av0.x; As_[(kq + 1) * STR + r0] = av0.y;   \
        As_[(kq + 2) * STR + r0] = av0.z; As_[(kq + 3) * STR + r0] = av0.w;   \
        As_[(kq + 0) * STR + r1] = av1.x; As_[(kq + 1) * STR + r1] = av1.y;   \
        As_[(kq + 2) * STR + r1] = av1.z; As_[(kq + 3) * STR + r1] = av1.w;   \
        Bs_[(kq + 0) * STR + r0] = bv0.x; Bs_[(kq + 1) * STR + r0] = bv0.y;   \
        Bs_[(kq + 2) * STR + r0] = bv0.z; Bs_[(kq + 3) * STR + r0] = bv0.w;   \
        Bs_[(kq + 0) * STR + r1] = bv1.x; Bs_[(kq + 1) * STR + r1] = bv1.y;   \
        Bs_[(kq + 2) * STR + r1] = bv1.z; Bs_[(kq + 3) * STR + r1] = bv1.w;   \
    } while (0)

#define COMPUTE(buf)                                                          \
    do {                                                                      \
        const float* As_ = sm + (buf) * 2 * STAGE_F;                          \
        const float* Bs_ = As_ + STAGE_F;                                     \
        _Pragma("unroll")                                                     \
        for (int k = 0; k < BK; k++) {                                        \
            float a[8], b[8];                                                 \
            float4 t0 = *(const float4*)&As_[k * STR + aRow];                 \
            float4 t1 = *(const float4*)&As_[k * STR + aRow + 4];             \
            a[0] = t0.x; a[1] = t0.y; a[2] = t0.z; a[3] = t0.w;               \
            a[4] = t1.x; a[5] = t1.y; a[6] = t1.z; a[7] = t1.w;               \
            float4 u0 = *(const float4*)&Bs_[k * STR + bCol];                 \
            float4 u1 = *(const float4*)&Bs_[k * STR + bCol + 4];             \
            b[0] = u0.x; b[1] = u0.y; b[2] = u0.z; b[3] = u0.w;               \
            b[4] = u1.x; b[5] = u1.y; b[6] = u1.z; b[7] = u1.w;               \
            _Pragma("unroll")                                                 \
            for (int ii = 0; ii < 8; ii++)                                    \
                _Pragma("unroll")                                             \
                for (int jj = 0; jj < 8; jj++)                                \
                    acc[ii][jj] = fmaf(a[ii], b[jj], acc[ii][jj]);            \
        }                                                                     \
    } while (0)

    // prologue: chunks 0,1,2 -> buffers 0,1,2
    LDG_CHUNK(0);
    STS_CHUNK(0);
    LDG_CHUNK(1);
    STS_CHUNK(1);
    LDG_CHUNK(2);
    STS_CHUNK(2);
    __syncthreads();

    const int NIT = K_DIM / BK;   // 128
#pragma unroll 1
    for (int it = 0, cb = 0; it < NIT; it += 3, cb ^= 3) {
        const int pb = cb ^ 3;    // prefetch buffer base

        if (it + 3 < NIT) LDG_CHUNK(it + 3);
        COMPUTE(cb + 0);
        if (it + 3 < NIT) STS_CHUNK(pb + 0);

        if (it + 4 < NIT) LDG_CHUNK(it + 4);
        if (it + 1 < NIT) COMPUTE(cb + 1);
        if (it + 4 < NIT) STS_CHUNK(pb + 1);

        if (it + 5 < NIT) LDG_CHUNK(it + 5);
        if (it + 2 < NIT) COMPUTE(cb + 2);
        if (it + 5 < NIT) STS_CHUNK(pb + 2);

        __syncthreads();   // one barrier per 3 iterations
    }

    // ---------------- fused epilogue: bias + LIF scan -----------------------
    float bb[8];
    {
        const float* bp = bias + colBase + bCol;
        float4 q0 = *(const float4*)(bp + 0);
        float4 q1 = *(const float4*)(bp + 4);
        bb[0] = q0.x; bb[1] = q0.y; bb[2] = q0.z; bb[3] = q0.w;
        bb[4] = q1.x; bb[5] = q1.y; bb[6] = q1.z; bb[7] = q1.w;
    }

    float* Cs = sm;   // 64 x CSTR floats = 33792 B <= 101376 B

#pragma unroll 1
    for (int half = 0; half < 2; half++) {
        if (wm == half) {
            const int rloc = lr * 8;
#pragma unroll
            for (int i = 0; i < 8; i++) {
                float* cp = Cs + (rloc + i) * CSTR + bCol;
                float4 v0, v1;
                v0.x = acc[i][0] + bb[0];
                v0.y = acc[i][1] + bb[1];
                v0.z = acc[i][2] + bb[2];
                v0.w = acc[i][3] + bb[3];
                v1.x = acc[i][4] + bb[4];
                v1.y = acc[i][5] + bb[5];
                v1.z = acc[i][6] + bb[6];
                v1.w = acc[i][7] + bb[7];
                *(float4*)(cp + 0) = v0;
                *(float4*)(cp + 4) = v1;
            }
        }
        __syncthreads();

        {
            const int blocal = tid >> 7;          // 0..1
            const int col    = tid & 127;         // 0..127
            const int bG     = blockIdx.y * 4 + half * 2 + blocal;
            float* ob = out + (size_t)bG * H_DIM + colBase + col;
            const float* cs = Cs + (blocal * 32) * CSTR + col;
            float v = 0.0f, cnt = 0.0f;
#pragma unroll
            for (int t = 0; t < T_STEPS; t++) {
                float x = cs[t * CSTR];
                v = __fadd_rn(v, __fmul_rn(__fsub_rn(x, v), 0.5f));
                bool fire = (v >= 1.0f);
                float s = fire ? 1.0f : 0.0f;
                ob[(size_t)t * BH] = s;
                cnt += s;
                v = fire ? 0.0f : v;
            }
            ob[(size_t)T_STEPS * BH] = cnt;       // count block after spk_seq
        }
        __syncthreads();
    }
}

// ---------------------------------------------------------------- launch
extern "C" void kernel_launch(void* const* d_in, const int* in_sizes, int n_in,
                              void* d_out, int out_size)
{
    const float* x_seq = (const float*)d_in[0];  // [T,B,F]
    const float* W     = (const float*)d_in[1];  // [H,F]
    const float* b     = (const float*)d_in[2];  // [H]
    float* out = (float*)d_out;

    cudaFuncSetAttribute(gemm_lif_fused,
                         cudaFuncAttributeMaxDynamicSharedMemorySize, SMEM_DYN);

    dim3 gg(N_DIM / BN, M_DIM / BM);   // (32, 64)
    gemm_lif_fused<<<gg, 256, SMEM_DYN>>>(x_seq, W, b, out);
}